// round 1
// baseline (speedup 1.0000x reference)
#include <cuda_runtime.h>

// RuleConstraintLoss: sparse op-gather + three masked reductions over states[B,L,D].
// inputs: states f32 [B,L,D], op_types i32 [B,M], op_before_pos i32 [B,M],
//         op_after_pos i32 [B,M], n_ops i32 [B]
// output: f32[4] = {total, identity_loss, cancel_loss, collapse_loss}

#define OP_IDENTITY     2
#define OP_CANCEL_START 3
#define OP_CANCEL_END   4
#define OP_STAR_ZERO    5
#define EPSF 1e-9f

// slot 0: identity, slot 1: cancel, slot 2: collapse
__device__ double g_sum[3];
__device__ int    g_cnt[3];

__global__ void rcl_init_kernel() {
    int t = threadIdx.x;
    if (t < 3) { g_sum[t] = 0.0; g_cnt[t] = 0; }
}

// 128 threads/block, D = 512 -> each thread owns one float4 of each row.
template<int D>
__global__ void rcl_op_kernel(const float* __restrict__ states,
                              const int*   __restrict__ op_types,
                              const int*   __restrict__ bp,
                              const int*   __restrict__ ap,
                              const int*   __restrict__ n_ops,
                              int L, int M) {
    const int gm  = blockIdx.x;
    const int b   = gm / M;
    const int m   = gm - b * M;
    const int tid = threadIdx.x;

    const int n = n_ops[b];
    if (m >= n) return;

    const int idx = b * M + m;
    const int ot  = op_types[idx];
    if (ot != OP_IDENTITY && ot != OP_CANCEL_START && ot != OP_STAR_ZERO) return;

    const int bpos = bp[idx];
    const int apos = ap[idx];
    if (bpos < 0 || bpos >= L || apos < 0 || apos >= L) return;

    __shared__ float s_red[8];  // 4 warps x up to 2 values

    const float4* rowB =
        (const float4*)(states + ((size_t)b * L + (size_t)bpos) * D);

    if (ot == OP_STAR_ZERO) {
        // collapse: relu( ent(after) - ent(before) + 0.5 )
        const float4* rowA =
            (const float4*)(states + ((size_t)b * L + (size_t)apos) * D);
        float4 a = rowA[tid];
        float4 c = rowB[tid];
        float ea = a.x*a.x + a.y*a.y + a.z*a.z + a.w*a.w;
        float eb = c.x*c.x + c.y*c.y + c.z*c.z + c.w*c.w;
        // block-reduce (ea, eb)
        #pragma unroll
        for (int o = 16; o > 0; o >>= 1) {
            ea += __shfl_down_sync(0xffffffffu, ea, o);
            eb += __shfl_down_sync(0xffffffffu, eb, o);
        }
        int w = tid >> 5;
        if ((tid & 31) == 0) { s_red[w] = ea; s_red[4 + w] = eb; }
        __syncthreads();
        float Ea = s_red[0] + s_red[1] + s_red[2] + s_red[3];
        float Eb = s_red[4] + s_red[5] + s_red[6] + s_red[7];
        float invA = 1.0f / (Ea + EPSF);
        float invB = 1.0f / (Eb + EPSF);
        // entropy terms: -sum p*log2(p+eps)
        float ha = 0.f, hb = 0.f;
        {
            float e, p;
            e = a.x*a.x; p = e*invA; ha -= p * __log2f(p + EPSF);
            e = a.y*a.y; p = e*invA; ha -= p * __log2f(p + EPSF);
            e = a.z*a.z; p = e*invA; ha -= p * __log2f(p + EPSF);
            e = a.w*a.w; p = e*invA; ha -= p * __log2f(p + EPSF);
            e = c.x*c.x; p = e*invB; hb -= p * __log2f(p + EPSF);
            e = c.y*c.y; p = e*invB; hb -= p * __log2f(p + EPSF);
            e = c.z*c.z; p = e*invB; hb -= p * __log2f(p + EPSF);
            e = c.w*c.w; p = e*invB; hb -= p * __log2f(p + EPSF);
        }
        __syncthreads();  // reuse s_red
        #pragma unroll
        for (int o = 16; o > 0; o >>= 1) {
            ha += __shfl_down_sync(0xffffffffu, ha, o);
            hb += __shfl_down_sync(0xffffffffu, hb, o);
        }
        if ((tid & 31) == 0) { s_red[w] = ha; s_red[4 + w] = hb; }
        __syncthreads();
        if (tid == 0) {
            float enta = s_red[0] + s_red[1] + s_red[2] + s_red[3];
            float entb = s_red[4] + s_red[5] + s_red[6] + s_red[7];
            float term = enta - entb + 0.5f;
            term = term > 0.f ? term : 0.f;
            atomicAdd(&g_sum[2], (double)term);
            atomicAdd(&g_cnt[2], 1);
        }
        return;
    }

    // identity or cancel: mse(target_row, before_row)
    int tpos;
    int slot;
    if (ot == OP_IDENTITY) {
        tpos = apos;
        slot = 0;
    } else {
        // cancel start: need next op within n, type END, ap_next in [0, L)
        if (m + 1 >= n || m + 1 >= M) return;
        int otn = op_types[idx + 1];
        int apn = ap[idx + 1];
        if (otn != OP_CANCEL_END || apn < 0 || apn >= L) return;
        tpos = apn;
        slot = 1;
    }
    const float4* rowA =
        (const float4*)(states + ((size_t)b * L + (size_t)tpos) * D);
    float4 a = rowA[tid];
    float4 c = rowB[tid];
    float d0 = a.x - c.x, d1 = a.y - c.y, d2 = a.z - c.z, d3 = a.w - c.w;
    float s = d0*d0 + d1*d1 + d2*d2 + d3*d3;
    #pragma unroll
    for (int o = 16; o > 0; o >>= 1)
        s += __shfl_down_sync(0xffffffffu, s, o);
    int w = tid >> 5;
    if ((tid & 31) == 0) s_red[w] = s;
    __syncthreads();
    if (tid == 0) {
        float tot = (s_red[0] + s_red[1] + s_red[2] + s_red[3]) * (1.0f / (float)D);
        atomicAdd(&g_sum[slot], (double)tot);
        atomicAdd(&g_cnt[slot], 1);
    }
}

__global__ void rcl_finalize_kernel(float* __restrict__ out) {
    if (threadIdx.x == 0) {
        int c0 = g_cnt[0] > 0 ? g_cnt[0] : 1;
        int c1 = g_cnt[1] > 0 ? g_cnt[1] : 1;
        int c2 = g_cnt[2] > 0 ? g_cnt[2] : 1;
        float id = (float)(g_sum[0] / (double)c0);
        float ca = (float)(g_sum[1] / (double)c1);
        float co = (float)(g_sum[2] / (double)c2);
        out[0] = 1.0f * id + 1.0f * ca + 0.5f * co;
        out[1] = id;
        out[2] = ca;
        out[3] = co;
    }
}

extern "C" void kernel_launch(void* const* d_in, const int* in_sizes, int n_in,
                              void* d_out, int out_size) {
    const float* states   = (const float*)d_in[0];
    const int*   op_types = (const int*)d_in[1];
    const int*   bp       = (const int*)d_in[2];
    const int*   ap       = (const int*)d_in[3];
    const int*   n_ops    = (const int*)d_in[4];

    const int B = in_sizes[4];
    const int M = in_sizes[1] / B;
    const int D = 512;
    const int L = in_sizes[0] / (B * D);

    rcl_init_kernel<<<1, 32>>>();
    rcl_op_kernel<512><<<B * M, 128>>>(states, op_types, bp, ap, n_ops, L, M);
    rcl_finalize_kernel<<<1, 32>>>((float*)d_out);
}